// round 13
// baseline (speedup 1.0000x reference)
#include <cuda_runtime.h>
#include <cuda_bf16.h>
#include <math.h>
#include <stdint.h>

// ---------------- problem dims ----------------
#define BB    4
#define SS    4096
#define HH    2048
#define VV    32000
#define IDIM  64
#define NLC   8192
#define NROWS (BB * SS)          // 16384
#define K2    192                // split-K concat: A=[hi|hi|lo], B=[hi|lo|hi]
#define NB_PREP 148

// ---------------- device scratch ----------------
__device__ int g_winner[NROWS];
__device__ int g_slot[NROWS];
__device__ int g_widx[NROWS];
__device__ int g_count;
__device__ unsigned g_bar1 = 0, g_bar2 = 0;
__device__ int g_prep_done = 0;
__device__ __align__(16) __nv_bfloat16 g_a2 [NLC * K2];   // activations, K-concat split
__device__ __align__(16) __nv_bfloat16 g_b2T[HH * K2];    // Wout^T, K-concat split, [n][k]

// ---------------- helpers ----------------
__device__ __forceinline__ float gelu_exact(float x) {
    return 0.5f * x * (1.0f + erff(x * 0.70710678118654752440f));
}
__device__ __forceinline__ float2 ffma2(float2 a, float2 b, float2 c) {
    unsigned long long ra, rb, rc, rd;
    ra = *reinterpret_cast<unsigned long long*>(&a);
    rb = *reinterpret_cast<unsigned long long*>(&b);
    rc = *reinterpret_cast<unsigned long long*>(&c);
    asm("fma.rn.f32x2 %0, %1, %2, %3;" : "=l"(rd) : "l"(ra), "l"(rb), "l"(rc));
    return *reinterpret_cast<float2*>(&rd);
}
__device__ __forceinline__ uint32_t smem_u32(const void* p) {
    uint32_t a;
    asm("{ .reg .u64 t; cvta.to.shared.u64 t, %1; cvt.u32.u64 %0, t; }" : "=r"(a) : "l"(p));
    return a;
}
__device__ __forceinline__ void ldm_x4(uint32_t* r, uint32_t addr) {
    asm volatile("ldmatrix.sync.aligned.m8n8.x4.shared.b16 {%0,%1,%2,%3}, [%4];"
        : "=r"(r[0]), "=r"(r[1]), "=r"(r[2]), "=r"(r[3]) : "r"(addr));
}
__device__ __forceinline__ void mma16816(float* c, const uint32_t* a, uint32_t b0, uint32_t b1) {
    asm volatile("mma.sync.aligned.m16n8k16.row.col.f32.bf16.bf16.f32 "
        "{%0,%1,%2,%3}, {%4,%5,%6,%7}, {%8,%9}, {%0,%1,%2,%3};"
        : "+f"(c[0]), "+f"(c[1]), "+f"(c[2]), "+f"(c[3])
        : "r"(a[0]), "r"(a[1]), "r"(a[2]), "r"(a[3]), "r"(b0), "r"(b1));
}

// grid barrier for a resident 148-block grid; counter-based, one arrival per block
__device__ __forceinline__ void grid_bar(unsigned* bar) {
    __syncthreads();
    __threadfence();
    if (threadIdx.x == 0) {
        atomicAdd(bar, 1u);
        while (atomicAdd(bar, 0u) < NB_PREP) { }
    }
    __syncthreads();
    __threadfence();
}

// ---------------- kernel 1: fused init + winner + compact (148 resident blocks) ----------
__global__ void __launch_bounds__(256) k_prep(const int* __restrict__ pos_b,
                                              const int* __restrict__ pos_s) {
    const int gt = blockIdx.x * 256 + threadIdx.x;   // 0 .. 37887

    // phase 1: init winner table + counter
    if (gt < NROWS) g_winner[gt] = -1;
    if (gt == 0) g_count = 0;
    grid_bar(&g_bar1);

    // phase 2: last-update-wins winner selection (JAX scatter semantics)
    if (gt < NLC) {
        int slot = pos_b[gt] * SS + pos_s[gt];
        atomicMax(&g_winner[slot], gt);
    }
    grid_bar(&g_bar2);

    // phase 3: compact (slot, winner) pairs
    if (gt < NROWS) {
        int w = g_winner[gt];
        if (w >= 0) {
            int p = atomicAdd(&g_count, 1);
            g_slot[p] = gt;
            g_widx[p] = w;
        }
    }

    // self-reset for deterministic graph replay: last block clears the counters
    __syncthreads();
    if (threadIdx.x == 0) {
        int v = atomicAdd(&g_prep_done, 1);
        if (v == NB_PREP - 1) {
            g_bar1 = 0; g_bar2 = 0; g_prep_done = 0;
            __threadfence();
        }
    }
}

// ---------------- kernel 2: fused MLP (bids 0-255) + Wout split (bids 256-767) --------
#define MLP_E 32
__global__ void __launch_bounds__(256) k_aux(const float* __restrict__ lc,
                      const float* __restrict__ W0, const float* __restrict__ b0,
                      const float* __restrict__ W1, const float* __restrict__ b1,
                      const float* __restrict__ W2, const float* __restrict__ b2,
                      const float* __restrict__ Wout) {
    const int tid = threadIdx.x;

    if (blockIdx.x >= 256) {
        // ---- Wout split + transpose -> K-concat [n][192]: [hi | lo | hi] ----
        int idx = (blockIdx.x - 256) * 256 + tid;        // over HH*IDIM = 131072
        if (idx < HH * IDIM) {
            int n = idx >> 6, k = idx & 63;
            float w = Wout[k * HH + n];
            __nv_bfloat16 h = __float2bfloat16(w);
            __nv_bfloat16 l = __float2bfloat16(w - __bfloat162float(h));
            size_t rb = (size_t)n * K2;
            g_b2T[rb +       k] = h;
            g_b2T[rb +  64 + k] = l;
            g_b2T[rb + 128 + k] = h;
        }
        return;
    }

    // ---- MLP 1->64->64->64, emit K-concat split-bf16: [hi | hi | lo] ----
    __shared__ float AT[IDIM][MLP_E + 2];
    __shared__ float Wsh[IDIM * IDIM];
    __shared__ float xsh[MLP_E];

    const int f4  = tid & 15;
    const int eg  = tid >> 4;
    const int j0  = f4 * 4;
    const int e0  = blockIdx.x * MLP_E;

    if (tid < MLP_E) xsh[tid] = lc[e0 + tid];
    {
        const float4* src = reinterpret_cast<const float4*>(W1);
        float4* dst = reinterpret_cast<float4*>(Wsh);
        #pragma unroll
        for (int i = 0; i < 4; i++) dst[tid + 256 * i] = src[tid + 256 * i];
    }
    __syncthreads();

    #pragma unroll
    for (int r = 0; r < 4; r++) {
        int k = j0 + r;
        float w = W0[k], b = b0[k];
        float v0 = gelu_exact(fmaf(xsh[2 * eg],     w, b));
        float v1 = gelu_exact(fmaf(xsh[2 * eg + 1], w, b));
        *reinterpret_cast<float2*>(&AT[k][2 * eg]) = make_float2(v0, v1);
    }
    __syncthreads();

    float2 acc[4];
    {
        float4 bb = *reinterpret_cast<const float4*>(b1 + j0);
        acc[0] = make_float2(bb.x, bb.x); acc[1] = make_float2(bb.y, bb.y);
        acc[2] = make_float2(bb.z, bb.z); acc[3] = make_float2(bb.w, bb.w);
        #pragma unroll 8
        for (int k = 0; k < IDIM; k++) {
            float2 a2 = *reinterpret_cast<float2*>(&AT[k][2 * eg]);
            float4 w4 = *reinterpret_cast<float4*>(&Wsh[k * IDIM + j0]);
            acc[0] = ffma2(a2, make_float2(w4.x, w4.x), acc[0]);
            acc[1] = ffma2(a2, make_float2(w4.y, w4.y), acc[1]);
            acc[2] = ffma2(a2, make_float2(w4.z, w4.z), acc[2]);
            acc[3] = ffma2(a2, make_float2(w4.w, w4.w), acc[3]);
        }
    }
    __syncthreads();

    #pragma unroll
    for (int f = 0; f < 4; f++) {
        *reinterpret_cast<float2*>(&AT[j0 + f][2 * eg]) =
            make_float2(gelu_exact(acc[f].x), gelu_exact(acc[f].y));
    }
    {
        const float4* src = reinterpret_cast<const float4*>(W2);
        float4* dst = reinterpret_cast<float4*>(Wsh);
        #pragma unroll
        for (int i = 0; i < 4; i++) dst[tid + 256 * i] = src[tid + 256 * i];
    }
    __syncthreads();

    {
        float4 bb = *reinterpret_cast<const float4*>(b2 + j0);
        acc[0] = make_float2(bb.x, bb.x); acc[1] = make_float2(bb.y, bb.y);
        acc[2] = make_float2(bb.z, bb.z); acc[3] = make_float2(bb.w, bb.w);
        #pragma unroll 8
        for (int k = 0; k < IDIM; k++) {
            float2 a2 = *reinterpret_cast<float2*>(&AT[k][2 * eg]);
            float4 w4 = *reinterpret_cast<float4*>(&Wsh[k * IDIM + j0]);
            acc[0] = ffma2(a2, make_float2(w4.x, w4.x), acc[0]);
            acc[1] = ffma2(a2, make_float2(w4.y, w4.y), acc[1]);
            acc[2] = ffma2(a2, make_float2(w4.z, w4.z), acc[2]);
            acc[3] = ffma2(a2, make_float2(w4.w, w4.w), acc[3]);
        }
    }

    #pragma unroll
    for (int half = 0; half < 2; half++) {
        float v[4];
        v[0] = gelu_exact(half ? acc[0].y : acc[0].x);
        v[1] = gelu_exact(half ? acc[1].y : acc[1].x);
        v[2] = gelu_exact(half ? acc[2].y : acc[2].x);
        v[3] = gelu_exact(half ? acc[3].y : acc[3].x);
        __nv_bfloat16 h[4], l[4];
        #pragma unroll
        for (int f = 0; f < 4; f++) {
            h[f] = __float2bfloat16(v[f]);
            l[f] = __float2bfloat16(v[f] - __bfloat162float(h[f]));
        }
        size_t rb = (size_t)(e0 + 2 * eg + half) * K2;
        uint2 hb = *reinterpret_cast<uint2*>(h);
        uint2 lb = *reinterpret_cast<uint2*>(l);
        *reinterpret_cast<uint2*>(&g_a2[rb +       j0]) = hb;
        *reinterpret_cast<uint2*>(&g_a2[rb +  64 + j0]) = hb;
        *reinterpret_cast<uint2*>(&g_a2[rb + 128 + j0]) = lb;
    }
}

// ---------------- kernel 3: HYBRID — persistent embed blocks + HMMA gemm blocks ------
// Odd bids < 2*NE are embed (NE=148, one per SM in wave 1, interleaved with gemm);
// everything else is a gemm tile. Structural DRAM/tensor overlap — no stream games.
#define NE        148
#define GEMM_TILES ((HH / 128) * (NLC / 128))          // 16 * 64 = 1024
#define HYB_GRID  (2 * NE + (GEMM_TILES - NE))         // 1172
#define GS_STRIDE 200
#define GEMM_SMEM (2 * 128 * GS_STRIDE * 2)            // 102400 B
extern __shared__ __nv_bfloat16 gsm2[];

__global__ void __launch_bounds__(256) k_hybrid(const int* __restrict__ ids,
                                                const float* __restrict__ wte,
                                                const float* __restrict__ bout,
                                                float* __restrict__ out) {
    const int bid = blockIdx.x;
    const int tid = threadIdx.x;

    if (bid < 2 * NE && (bid & 1)) {
        // ================= EMBED role: persistent, warp per row =================
        const int eb    = bid >> 1;
        const int lane  = tid & 31;
        const int warp  = (eb * 256 + tid) >> 5;
        const int nwarp = NE * 8;

        for (int row = warp; row < NROWS; row += nwarp) {
            if (g_winner[row] >= 0) continue;          // overwritten by gemm epilogue
            int id = ids[row];
            id = max(0, min(id, VV - 1));
            const float4* __restrict__ src = reinterpret_cast<const float4*>(wte + (size_t)id * HH);
            float4*       __restrict__ dst = reinterpret_cast<float4*>(out + (size_t)row * HH);
            #pragma unroll
            for (int h = 0; h < 2; h++) {
                float4 v[8];
                #pragma unroll
                for (int i = 0; i < 8; i++) v[i] = src[lane + 32 * (8 * h + i)];
                #pragma unroll
                for (int i = 0; i < 8; i++) __stcs(&dst[lane + 32 * (8 * h + i)], v[i]);
            }
        }
        return;
    }

    // ================= GEMM role: [count x 192] @ [192 x 2048] + scatter ============
    const int gid = (bid < 2 * NE) ? (bid >> 1) : (bid - NE);   // 0..1023
    const int count = g_count;
    const int m0 = (gid >> 4) * 128;
    if (m0 >= count) return;
    const int n0 = (gid & 15) * 128;

    __nv_bfloat16* As = gsm2;
    __nv_bfloat16* Bs = gsm2 + 128 * GS_STRIDE;

    // stage A (gathered rows) and B: thread t -> row t>>1, half t&1, 12 uint4 each
    {
        int r = tid >> 1, h = tid & 1;
        int row = m0 + r;
        const uint4* srcA = nullptr;
        if (row < count)
            srcA = reinterpret_cast<const uint4*>(g_a2 + (size_t)g_widx[row] * K2) + h * 12;
        uint4* dstA = reinterpret_cast<uint4*>(As + r * GS_STRIDE + h * 96);
        const uint4* srcB = reinterpret_cast<const uint4*>(g_b2T + (size_t)(n0 + r) * K2) + h * 12;
        uint4* dstB = reinterpret_cast<uint4*>(Bs + r * GS_STRIDE + h * 96);
        #pragma unroll
        for (int c = 0; c < 12; c++) {
            dstA[c] = srcA ? srcA[c] : make_uint4(0u, 0u, 0u, 0u);
            dstB[c] = srcB[c];
        }
    }
    __syncthreads();

    const int wid  = tid >> 5;
    const int lane = tid & 31;
    const int mg   = wid & 3;        // m-group: rows mg*32 .. +31
    const int ng   = wid >> 2;       // n-group: cols ng*64 .. +63

    uint32_t aAddr = smem_u32(As) +
        (uint32_t)(((mg * 32 + (lane & 15)) * GS_STRIDE + (lane >> 4) * 8) * 2);
    uint32_t bAddr = smem_u32(Bs) +
        (uint32_t)(((ng * 64 + (lane & 7) + ((lane >> 4) << 3)) * GS_STRIDE +
                    (((lane >> 3) & 1) << 3)) * 2);

    float acc[2][8][4];
    #pragma unroll
    for (int am = 0; am < 2; am++)
        #pragma unroll
        for (int ns = 0; ns < 8; ns++)
            #pragma unroll
            for (int c = 0; c < 4; c++) acc[am][ns][c] = 0.f;

    #pragma unroll 1
    for (int ks = 0; ks < K2 / 16; ks++) {
        uint32_t aF0[4], aF1[4], bF[4][4];
        ldm_x4(aF0, aAddr);
        ldm_x4(aF1, aAddr + 16 * GS_STRIDE * 2);
        #pragma unroll
        for (int p = 0; p < 4; p++) ldm_x4(bF[p], bAddr + p * 16 * GS_STRIDE * 2);
        aAddr += 32;
        bAddr += 32;
        #pragma unroll
        for (int p = 0; p < 4; p++) {
            mma16816(acc[0][2 * p],     aF0, bF[p][0], bF[p][1]);
            mma16816(acc[0][2 * p + 1], aF0, bF[p][2], bF[p][3]);
            mma16816(acc[1][2 * p],     aF1, bF[p][0], bF[p][1]);
            mma16816(acc[1][2 * p + 1], aF1, bF[p][2], bF[p][3]);
        }
    }

    // epilogue: scatter rows via g_slot, add bias
    #pragma unroll
    for (int am = 0; am < 2; am++) {
        int r = m0 + mg * 32 + am * 16 + (lane >> 2);
        int s0 = (r     < count) ? g_slot[r]     : -1;
        int s1 = (r + 8 < count) ? g_slot[r + 8] : -1;
        #pragma unroll
        for (int ns = 0; ns < 8; ns++) {
            int col = n0 + ng * 64 + ns * 8 + (lane & 3) * 2;
            float2 bv = *reinterpret_cast<const float2*>(bout + col);
            if (s0 >= 0) {
                float2 v = make_float2(acc[am][ns][0] + bv.x, acc[am][ns][1] + bv.y);
                *reinterpret_cast<float2*>(out + (size_t)s0 * HH + col) = v;
            }
            if (s1 >= 0) {
                float2 v = make_float2(acc[am][ns][2] + bv.x, acc[am][ns][3] + bv.y);
                *reinterpret_cast<float2*>(out + (size_t)s1 * HH + col) = v;
            }
        }
    }
}

// ---------------- stream/event for the aux fork ----------------
static cudaStream_t s_aux = nullptr;
static cudaEvent_t ev_start, ev_aux;
namespace {
struct HxInit {
    HxInit() {
        cudaStreamCreateWithFlags(&s_aux, cudaStreamNonBlocking);
        cudaEventCreateWithFlags(&ev_start, cudaEventDisableTiming);
        cudaEventCreateWithFlags(&ev_aux,   cudaEventDisableTiming);
        cudaFuncSetAttribute(k_hybrid, cudaFuncAttributeMaxDynamicSharedMemorySize, GEMM_SMEM);
    }
};
HxInit hx_init_;
}

// ---------------- launcher ----------------
extern "C" void kernel_launch(void* const* d_in, const int* in_sizes, int n_in,
                              void* d_out, int out_size) {
    const int*   input_ids = (const int*)  d_in[0];
    const float* lc        = (const float*)d_in[1];
    const int*   pos_b     = (const int*)  d_in[2];
    const int*   pos_s     = (const int*)  d_in[3];
    const float* wte       = (const float*)d_in[4];
    const float* W0        = (const float*)d_in[5];
    const float* b0        = (const float*)d_in[6];
    const float* W1        = (const float*)d_in[7];
    const float* b1        = (const float*)d_in[8];
    const float* W2        = (const float*)d_in[9];
    const float* b2        = (const float*)d_in[10];
    const float* Wout      = (const float*)d_in[11];
    const float* bout      = (const float*)d_in[12];
    float* out = (float*)d_out;

    // fork: MLP + Wout split (independent of winner table)
    cudaEventRecord(ev_start, 0);
    cudaStreamWaitEvent(s_aux, ev_start, 0);
    k_aux<<<768, 256, 0, s_aux>>>(lc, W0, b0, W1, b1, W2, b2, Wout);
    cudaEventRecord(ev_aux, s_aux);

    // main: fused init + winner + compact (one resident-grid launch)
    k_prep<<<NB_PREP, 256>>>(pos_b, pos_s);

    // join aux, then the single hybrid kernel does embed + gemm with built-in overlap
    cudaStreamWaitEvent(0, ev_aux, 0);
    k_hybrid<<<HYB_GRID, 256, GEMM_SMEM>>>(input_ids, wte, bout, out);
}